// round 11
// baseline (speedup 1.0000x reference)
#include <cuda_runtime.h>
#include <math.h>

#define NLOC 1940
#define NPRI 8732
#define BATCH 16
#define TOPK 10
#define NOBJ (BATCH*TOPK)
#define DS 64
#define IMG 300
#define ZWHAT 64
#define CPAD 4
#define TILE 16
#define NTX ((IMG + TILE - 1) / TILE)   // 19

typedef unsigned long long ull;

// ---------------- device scratch (no allocation allowed) -------------------
__device__ __align__(16) float g_decoded[NOBJ * CPAD * DS * DS];   // 10.5 MB
__device__ int   g_order[BATCH * TOPK];
__device__ __align__(16) float g_act0[NOBJ * 256 * 4];    // L0 out [c][y][x], 640 KB
__device__ __align__(16) float g_act1[NOBJ * 128 * 16];   // L1 out [c][4][4], 1.3 MB
__device__ __align__(16) float g_act3[NOBJ * 32 * 16 * 16];  // L3 out, 5.2 MB

// ---------------- f32x2 helpers --------------------------------------------
__device__ __forceinline__ ull pack2(float lo, float hi) {
    ull r; asm("mov.b64 %0, {%1, %2};" : "=l"(r) : "f"(lo), "f"(hi)); return r;
}
__device__ __forceinline__ void unpack2(ull v, float& a, float& b) {
    asm("mov.b64 {%0, %1}, %2;" : "=f"(a), "=f"(b) : "l"(v));
}
__device__ __forceinline__ ull ffma2(ull a, ull b, ull c) {
    ull d; asm("fma.rn.f32x2 %0, %1, %2, %3;" : "=l"(d) : "l"(a), "l"(b), "l"(c));
    return d;
}
__device__ __forceinline__ ull relu2(ull v) {
    float a, b; unpack2(v, a, b);
    return pack2(fmaxf(a, 0.f), fmaxf(b, 0.f));
}

// ---------------- index maps ------------------------------------------------
__device__ __forceinline__ int prior_to_loc(int i) {
    if (i < 5776) return i >> 2;
    if (i < 7942) return 1444 + (i - 5776) / 6;
    if (i < 8542) return 1805 + (i - 7942) / 6;
    if (i < 8692) return 1905 + (i - 8542) / 6;
    if (i < 8728) return 1930 + ((i - 8692) >> 2);
    return 1939;
}
__device__ __forceinline__ void loc_to_priors(int l, int& start, int& bpl) {
    if (l < 1444)      { start = 4 * l;                 bpl = 4; }
    else if (l < 1805) { start = 5776 + 6 * (l - 1444); bpl = 6; }
    else if (l < 1905) { start = 7942 + 6 * (l - 1805); bpl = 6; }
    else if (l < 1930) { start = 8542 + 6 * (l - 1905); bpl = 6; }
    else               { start = 8692 + 4 * (l - 1930); bpl = 4; }
}
__device__ __forceinline__ bool better(float a, int ia, float b, int ib) {
    return a > b || (a == b && ia < ib);
}
__device__ __forceinline__ void insert3(float v, int i,
                                        float& v0, int& i0, float& v1, int& i1,
                                        float& v2, int& i2) {
    if (better(v, i, v0, i0)) { v2 = v1; i2 = i1; v1 = v0; i1 = i0; v0 = v; i0 = i; }
    else if (better(v, i, v1, i1)) { v2 = v1; i2 = i1; v1 = v; i1 = i; }
    else if (better(v, i, v2, i2)) { v2 = v; i2 = i; }
}

// block-redundant top-3 locations of batch b -> prior index of rank j.
// scratch: 1536 floats of shared.
__device__ __forceinline__ int block_topk(const float* __restrict__ z_depth,
                                          int b, int j, float* scratch) {
    const int tid = threadIdx.x;
    float (*sv)[3] = (float(*)[3])scratch;
    int   (*si)[3] = (int(*)[3])(scratch + 256 * 3);

    float v0 = -INFINITY, v1 = -INFINITY, v2 = -INFINITY;
    int   i0 = 0x7fffffff, i1 = 0x7fffffff, i2 = 0x7fffffff;
    const float4* __restrict__ zd4 =
        reinterpret_cast<const float4*>(z_depth + b * NLOC);
    for (int i = tid; i < NLOC / 4; i += 256) {
        const float4 v = __ldg(zd4 + i);
        insert3(v.x, 4 * i + 0, v0, i0, v1, i1, v2, i2);
        insert3(v.y, 4 * i + 1, v0, i0, v1, i1, v2, i2);
        insert3(v.z, 4 * i + 2, v0, i0, v1, i1, v2, i2);
        insert3(v.w, 4 * i + 3, v0, i0, v1, i1, v2, i2);
    }
    sv[tid][0] = v0; sv[tid][1] = v1; sv[tid][2] = v2;
    si[tid][0] = i0; si[tid][1] = i1; si[tid][2] = i2;
    __syncthreads();
    for (int s = 128; s > 0; s >>= 1) {
        if (tid < s) {
            #pragma unroll
            for (int q = 0; q < 3; q++)
                insert3(sv[tid + s][q], si[tid + s][q], v0, i0, v1, i1, v2, i2);
            sv[tid][0] = v0; sv[tid][1] = v1; sv[tid][2] = v2;
            si[tid][0] = i0; si[tid][1] = i1; si[tid][2] = i2;
        }
        __syncthreads();
    }
    __shared__ int s_ord;
    if (tid == 0) {
        int ranks[3] = { i0, i1, i2 };
        int ord = -1, cnt = 0;
        #pragma unroll
        for (int r = 0; r < 3; r++) {
            int start, bpl;
            loc_to_priors(ranks[r], start, bpl);
            if (ord < 0 && j < cnt + bpl) ord = start + (j - cnt);
            cnt += bpl;
        }
        s_ord = ord;
    }
    __syncthreads();
    return s_ord;
}

// ---------------------------------------------------------------------------
// K1: topk + L0 (64 -> 256 ch, 1x1 -> 2x2). grid = NOBJ, 256 threads.
// ---------------------------------------------------------------------------
__global__ void __launch_bounds__(256) k1_topk_l0(
    const float* __restrict__ z_depth,
    const float* __restrict__ z_what,
    const float* __restrict__ W0, const float* __restrict__ b0)
{
    __shared__ __align__(16) float scr[1536];
    __shared__ __align__(16) float s_zw[ZWHAT];

    const int m = blockIdx.x;
    const int b = m / TOPK;
    const int j = m % TOPK;

    const int ord = block_topk(z_depth, b, j, scr);
    if (threadIdx.x == 0) g_order[m] = ord;

    const int loc = prior_to_loc(ord);
    const float* src = z_what + (size_t)(b * NLOC + loc) * ZWHAT;
    if (threadIdx.x < ZWHAT) s_zw[threadIdx.x] = src[threadIdx.x];
    __syncthreads();

    const int o = threadIdx.x;   // 256 output channels
    const ulonglong2* __restrict__ W0q = reinterpret_cast<const ulonglong2*>(W0);
    const float bo = __ldg(b0 + o);
    ull acc01 = pack2(bo, bo), acc23 = acc01;
    #pragma unroll 8
    for (int c = 0; c < 64; c++) {
        const ulonglong2 wq = __ldg(W0q + c * 256 + o);
        const ull ivd = pack2(s_zw[c], s_zw[c]);
        acc01 = ffma2(ivd, wq.x, acc01);
        acc23 = ffma2(ivd, wq.y, acc23);
    }
    ull* ob = reinterpret_cast<ull*>(g_act0) + (size_t)m * 512 + o * 2;
    ob[0] = relu2(acc01);   // out[o][0][0..1]
    ob[1] = relu2(acc23);   // out[o][1][0..1]
}

// ---------------------------------------------------------------------------
// K2: L1 (256 -> 128 ch, 2x2 -> 4x4), split over output-channel quartiles.
// grid = NOBJ*4, 128 threads. Block (m,k) computes out channels [32k, 32k+32).
// ---------------------------------------------------------------------------
__global__ void __launch_bounds__(128) k2_l1(
    const float* __restrict__ W1, const float* __restrict__ b1)
{
    __shared__ __align__(16) float s_in[1024];   // L0 out [c∈256][y][x]

    const int m = blockIdx.x >> 2;
    const int k = blockIdx.x & 3;
    const int tid = threadIdx.x;

    {
        const float4* __restrict__ a4 =
            reinterpret_cast<const float4*>(g_act0) + (size_t)m * 256;
        float4* s4 = reinterpret_cast<float4*>(s_in);
        s4[tid]       = __ldg(a4 + tid);
        s4[tid + 128] = __ldg(a4 + tid + 128);
    }
    __syncthreads();

    const int o = 32 * k + (tid & 31);
    const int p = tid >> 5;            // pixel 0..3: y=p>>1, x=p&1
    const ulonglong2* __restrict__ Wq = reinterpret_cast<const ulonglong2*>(W1);
    const float bo = __ldg(b1 + o);
    ull acc01 = pack2(bo, bo), acc23 = acc01;
    #pragma unroll 8
    for (int c = 0; c < 256; c++) {
        const ulonglong2 wq = __ldg(Wq + c * 128 + o);
        const float iv = s_in[c * 4 + p];
        const ull ivd = pack2(iv, iv);
        acc01 = ffma2(ivd, wq.x, acc01);
        acc23 = ffma2(ivd, wq.y, acc23);
    }
    const int y = p >> 1, x = p & 1;
    // g_act1 layout [o∈128][row∈4][col∈4]
    ull* o2 = reinterpret_cast<ull*>(g_act1) + (size_t)m * 1024 + o * 8;
    o2[(2 * y) * 2 + x]     = relu2(acc01);
    o2[(2 * y + 1) * 2 + x] = relu2(acc23);
}

// ---------------------------------------------------------------------------
// K3: L2+L3, split spatially. grid = NOBJ*4, 256 threads.
// Block (m,k): L2 input row k -> L2 out rows 2k..2k+1 -> L3 out rows 4k..4k+4.
// ---------------------------------------------------------------------------
__global__ void __launch_bounds__(256) k3_l2l3(
    const float* __restrict__ W2, const float* __restrict__ b2,
    const float* __restrict__ W3, const float* __restrict__ b3)
{
    __shared__ __align__(16) float s_in[512];    // L2 in row k: [c∈128][x∈4]
    __shared__ __align__(16) float s_l2[1024];   // L2 out: [o∈64][y2∈2][x∈8]

    const int m = blockIdx.x >> 2;
    const int k = blockIdx.x & 3;
    const int tid = threadIdx.x;

    if (tid < 128) {
        reinterpret_cast<float4*>(s_in)[tid] = __ldg(
            reinterpret_cast<const float4*>(g_act1 + (size_t)m * 2048 + tid * 16 + k * 4));
    }
    __syncthreads();

    // ---- L2: 128 -> 64 ch; thread = (o = tid%64, x = tid/64) ----
    {
        const int o = tid & 63;
        const int x = tid >> 6;        // 0..3
        const ulonglong2* __restrict__ Wq = reinterpret_cast<const ulonglong2*>(W2);
        const float bo = __ldg(b2 + o);
        ull acc01 = pack2(bo, bo), acc23 = acc01;
        #pragma unroll 8
        for (int c = 0; c < 128; c++) {
            const ulonglong2 wq = __ldg(Wq + c * 64 + o);
            const float iv = s_in[c * 4 + x];
            const ull ivd = pack2(iv, iv);
            acc01 = ffma2(ivd, wq.x, acc01);
            acc23 = ffma2(ivd, wq.y, acc23);
        }
        ull* sl = reinterpret_cast<ull*>(s_l2) + o * 8;
        sl[x]     = relu2(acc01);      // row y2=0, cols 2x..2x+1
        sl[4 + x] = relu2(acc23);      // row y2=1
    }
    __syncthreads();

    // ---- L3: 64 -> 32 ch; thread = (o=tid%32, y=(tid/32)%2, xq=tid/64) ----
    {
        const int o  = tid & 31;
        const int y  = (tid >> 5) & 1;
        const int xq = tid >> 6;       // 0..3; input px x = 2xq, 2xq+1
        const ulonglong2* __restrict__ Wq = reinterpret_cast<const ulonglong2*>(W3);
        const float bo = __ldg(b3 + o);
        const ull bb = pack2(bo, bo);
        ull acc01[2] = { bb, bb }, acc23[2] = { bb, bb };
        #pragma unroll 4
        for (int c = 0; c < 64; c++) {
            const ulonglong2 wq = __ldg(Wq + c * 32 + o);
            const ull iv2 = *reinterpret_cast<const ull*>(s_l2 + c * 16 + y * 8 + 2 * xq);
            float i0, i1; unpack2(iv2, i0, i1);
            const ull d0 = pack2(i0, i0);
            const ull d1 = pack2(i1, i1);
            acc01[0] = ffma2(d0, wq.x, acc01[0]);
            acc23[0] = ffma2(d0, wq.y, acc23[0]);
            acc01[1] = ffma2(d1, wq.x, acc01[1]);
            acc23[1] = ffma2(d1, wq.y, acc23[1]);
        }
        // g_act3 layout [o∈32][16][16]; out rows 4k+2y, 4k+2y+1
        float* base = g_act3 + (size_t)m * 8192 + o * 256;
        ull* row0 = reinterpret_cast<ull*>(base + (4 * k + 2 * y) * 16);
        ull* row1 = reinterpret_cast<ull*>(base + (4 * k + 2 * y + 1) * 16);
        row0[2 * xq]     = relu2(acc01[0]);
        row0[2 * xq + 1] = relu2(acc01[1]);
        row1[2 * xq]     = relu2(acc23[0]);
        row1[2 * xq + 1] = relu2(acc23[1]);
    }
}

// ---------------------------------------------------------------------------
// K4: L4 + L5 for one (object, row-slice). 4 blocks per object.
// ---------------------------------------------------------------------------
__global__ void __launch_bounds__(256) decodeB_kernel(
    const float* __restrict__ W4, const float* __restrict__ b4,
    const float* __restrict__ W5, const float* __restrict__ b5)
{
    __shared__ __align__(16) float s_in[32 * 4 * 16];    // L4 src slice, 8 KB
    __shared__ __align__(16) float s_mid[16 * 8 * 32];   // L4 out slice, 16 KB
    __shared__ __align__(16) float s_w5[16 * 3 * 4];
    __shared__ __align__(16) float s_b5[4];

    const int m = blockIdx.x >> 2;
    const int k = blockIdx.x & 3;
    const int tid = threadIdx.x;

    {
        const float4* __restrict__ a4 =
            reinterpret_cast<const float4*>(g_act3) + (size_t)m * 2048;
        float4* s4 = reinterpret_cast<float4*>(s_in);
        #pragma unroll
        for (int f = tid; f < 512; f += 256) {
            const int c = f >> 4, rr = (f >> 2) & 3, xq = f & 3;
            s4[f] = __ldg(a4 + c * 64 + (4 * k + rr) * 4 + xq);
        }
    }
    if (tid < 192) s_w5[tid] = __ldg(W5 + tid);
    if (tid < 3)   s_b5[tid] = __ldg(b5 + tid);
    __syncthreads();

    // ---- L4: 32 -> 16 ch (quadrant pairs) ----
    {
        const int o  = tid & 15;
        const int y  = (tid >> 4) & 3;
        const int x0 = (tid >> 6) * 4;
        const ulonglong2* __restrict__ W4q = reinterpret_cast<const ulonglong2*>(W4);
        const float bo = __ldg(b4 + o);
        const ull bb = pack2(bo, bo);
        ull acc01[4], acc23[4];
        #pragma unroll
        for (int p = 0; p < 4; p++) { acc01[p] = bb; acc23[p] = bb; }

        #pragma unroll 4
        for (int c = 0; c < 32; c++) {
            const ulonglong2 wq = __ldg(W4q + c * 16 + o);
            const ull* __restrict__ ivp =
                reinterpret_cast<const ull*>(s_in + c * 64 + y * 16 + x0);
            #pragma unroll
            for (int pp = 0; pp < 2; pp++) {
                float i0, i1; unpack2(ivp[pp], i0, i1);
                const ull d0 = pack2(i0, i0);
                const ull d1 = pack2(i1, i1);
                acc01[2 * pp]     = ffma2(d0, wq.x, acc01[2 * pp]);
                acc23[2 * pp]     = ffma2(d0, wq.y, acc23[2 * pp]);
                acc01[2 * pp + 1] = ffma2(d1, wq.x, acc01[2 * pp + 1]);
                acc23[2 * pp + 1] = ffma2(d1, wq.y, acc23[2 * pp + 1]);
            }
        }
        #pragma unroll
        for (int p = 0; p < 4; p++) {
            const int col = 2 * (x0 + p);
            *reinterpret_cast<ull*>(s_mid + o * 256 + (2 * y) * 32 + col)     = relu2(acc01[p]);
            *reinterpret_cast<ull*>(s_mid + o * 256 + (2 * y + 1) * 32 + col) = relu2(acc23[p]);
        }
    }
    __syncthreads();

    // ---- L5: 16 -> 3 ch, sigmoid, CPAD-interleaved texels ----
    {
        const int sy = tid >> 5;
        const int sx = tid & 31;
        const ulonglong2* __restrict__ w5u = reinterpret_cast<const ulonglong2*>(s_w5);
        ull acc01[3], acc23[3];
        #pragma unroll
        for (int o = 0; o < 3; o++) {
            acc01[o] = pack2(s_b5[o], s_b5[o]);
            acc23[o] = acc01[o];
        }
        #pragma unroll 4
        for (int c = 0; c < 16; c++) {
            const float iv = s_mid[c * 256 + sy * 32 + sx];
            const ull ivd = pack2(iv, iv);
            #pragma unroll
            for (int o = 0; o < 3; o++) {
                const ulonglong2 wq = w5u[c * 3 + o];
                acc01[o] = ffma2(ivd, wq.x, acc01[o]);
                acc23[o] = ffma2(ivd, wq.y, acc23[o]);
            }
        }
        float r00[3], r01[3], r10[3], r11[3];
        #pragma unroll
        for (int o = 0; o < 3; o++) {
            float v00, v01, v10, v11;
            unpack2(acc01[o], v00, v01);
            unpack2(acc23[o], v10, v11);
            r00[o] = 1.0f / (1.0f + __expf(-v00));
            r01[o] = 1.0f / (1.0f + __expf(-v01));
            r10[o] = 1.0f / (1.0f + __expf(-v10));
            r11[o] = 1.0f / (1.0f + __expf(-v11));
        }
        float4* g4 = reinterpret_cast<float4*>(g_decoded) + (size_t)m * DS * DS;
        const int row0 = 16 * k + 2 * sy;
        const int col0 = 2 * sx;
        g4[row0 * DS + col0]           = make_float4(r00[0], r00[1], r00[2], 0.f);
        g4[row0 * DS + col0 + 1]       = make_float4(r01[0], r01[1], r01[2], 0.f);
        g4[(row0 + 1) * DS + col0]     = make_float4(r10[0], r10[1], r10[2], 0.f);
        g4[(row0 + 1) * DS + col0 + 1] = make_float4(r11[0], r11[1], r11[2], 0.f);
    }
}

// ---------------------------------------------------------------------------
// K5: fused STN + depth-ordered first-nonzero compositing (unchanged).
// ---------------------------------------------------------------------------
__global__ void __launch_bounds__(256) composite_kernel(
    const float* __restrict__ z_where,
    const int*   __restrict__ z_present,
    float* __restrict__ out)
{
    const int b = blockIdx.y;
    const int tx0 = (blockIdx.x % NTX) * TILE;
    const int ty0 = (blockIdx.x / NTX) * TILE;

    __shared__ float s_sx[TOPK], s_ox[TOPK], s_sy[TOPK], s_oy[TOPK];
    __shared__ int   s_flag[TOPK];
    __shared__ int   s_list[TOPK];
    __shared__ int   s_nc;

    const int tid = threadIdx.x;
    if (tid < TOPK) {
        const int ord = g_order[b * TOPK + tid];
        const float* zw = z_where + (size_t)(b * NPRI + ord) * 4;
        const float cx = zw[0], cy = zw[1];
        const float w = zw[2] + 1e-6f, h = zw[3] + 1e-6f;
        const float half = (float)DS * 0.5f;
        const float xsn = half / w;
        const float ysn = half / h;
        const float sx = xsn * (2.0f / (float)IMG);
        const float ox = half - 0.5f
                         + xsn * ((1.0f / (float)IMG - 1.0f) - (2.0f * cx - 1.0f));
        const float sy = ysn * (2.0f / (float)IMG);
        const float oy = half - 0.5f
                         + ysn * ((1.0f / (float)IMG - 1.0f) - (2.0f * cy - 1.0f));
        s_sx[tid] = sx; s_ox[tid] = ox; s_sy[tid] = sy; s_oy[tid] = oy;
        const float ix_lo = fmaf((float)tx0, sx, ox);
        const float ix_hi = fmaf((float)(tx0 + TILE - 1), sx, ox);
        const float iy_lo = fmaf((float)ty0, sy, oy);
        const float iy_hi = fmaf((float)(ty0 + TILE - 1), sy, oy);
        const bool pres = (z_present[b * NPRI + ord] == 1);
        s_flag[tid] = (pres &&
                       ix_hi >= -1.01f && ix_lo < 64.01f &&
                       iy_hi >= -1.01f && iy_lo < 64.01f) ? 1 : 0;
    }
    __syncthreads();
    if (tid == 0) {
        int nc = 0;
        #pragma unroll
        for (int k = 0; k < TOPK; k++)
            if (s_flag[k]) s_list[nc++] = k;
        s_nc = nc;
    }
    __syncthreads();

    const int x = tx0 + (tid % TILE);
    const int y = ty0 + (tid / TILE);
    if (x >= IMG || y >= IMG) return;
    const float fx = (float)x, fy = (float)y;

    float r0 = 0.0f, r1 = 0.0f, r2 = 0.0f;
    int done = 0;
    const int nc = s_nc;

    for (int kk = 0; kk < nc; kk++) {
        const int k = s_list[kk];
        const float ix = fmaf(fx, s_sx[k], s_ox[k]);
        const float iy = fmaf(fy, s_sy[k], s_oy[k]);
        const float ix0f = floorf(ix), iy0f = floorf(iy);
        if (!(ix0f >= -1.0f && ix0f <= 63.0f && iy0f >= -1.0f && iy0f <= 63.0f))
            continue;
        const float wx1 = ix - ix0f, wy1 = iy - iy0f;
        const float wx0 = 1.0f - wx1, wy0 = 1.0f - wy1;
        const int ix0 = (int)ix0f, iy0 = (int)iy0f;
        const bool vx0 = (ix0 >= 0), vx1 = (ix0 <= 62);
        const bool vy0 = (iy0 >= 0), vy1 = (iy0 <= 62);
        const float w00 = (vy0 && vx0) ? wy0 * wx0 : 0.0f;
        const float w01 = (vy0 && vx1) ? wy0 * wx1 : 0.0f;
        const float w10 = (vy1 && vx0) ? wy1 * wx0 : 0.0f;
        const float w11 = (vy1 && vx1) ? wy1 * wx1 : 0.0f;
        const int x0c = max(ix0, 0),     x1c = min(ix0 + 1, DS - 1);
        const int y0c = max(iy0, 0),     y1c = min(iy0 + 1, DS - 1);
        const int i00 = y0c * DS + x0c, i01 = y0c * DS + x1c;
        const int i10 = y1c * DS + x0c, i11 = y1c * DS + x1c;
        const float4* __restrict__ base = reinterpret_cast<const float4*>(g_decoded)
                                          + (size_t)(b * TOPK + k) * DS * DS;
        const float4 t00 = __ldg(base + i00);
        const float4 t01 = __ldg(base + i01);
        const float4 t10 = __ldg(base + i10);
        const float4 t11 = __ldg(base + i11);

        const float s0 = t00.x * w00 + t01.x * w01 + t10.x * w10 + t11.x * w11;
        const float s1 = t00.y * w00 + t01.y * w01 + t10.y * w10 + t11.y * w11;
        const float s2 = t00.z * w00 + t01.z * w01 + t10.z * w10 + t11.z * w11;

        if (!(done & 1) && s0 != 0.0f) { r0 = s0; done |= 1; }
        if (!(done & 2) && s1 != 0.0f) { r1 = s1; done |= 2; }
        if (!(done & 4) && s2 != 0.0f) { r2 = s2; done |= 4; }
        if (done == 7) break;
    }

    const size_t pix = (size_t)y * IMG + x;
    out[((size_t)(b * 3 + 0) * IMG * IMG) + pix] = r0;
    out[((size_t)(b * 3 + 1) * IMG * IMG) + pix] = r1;
    out[((size_t)(b * 3 + 2) * IMG * IMG) + pix] = r2;
}

// ---------------------------------------------------------------------------
extern "C" void kernel_launch(void* const* d_in, const int* in_sizes, int n_in,
                              void* d_out, int out_size)
{
    const float* z_what    = (const float*)d_in[0];
    const float* z_where   = (const float*)d_in[1];
    const int*   z_present = (const int*)  d_in[2];
    const float* z_depth   = (const float*)d_in[3];
    const float* W0 = (const float*)d_in[4];  const float* b0 = (const float*)d_in[5];
    const float* W1 = (const float*)d_in[6];  const float* b1 = (const float*)d_in[7];
    const float* W2 = (const float*)d_in[8];  const float* b2 = (const float*)d_in[9];
    const float* W3 = (const float*)d_in[10]; const float* b3 = (const float*)d_in[11];
    const float* W4 = (const float*)d_in[12]; const float* b4 = (const float*)d_in[13];
    const float* W5 = (const float*)d_in[14]; const float* b5 = (const float*)d_in[15];
    float* out = (float*)d_out;

    k1_topk_l0<<<NOBJ, 256>>>(z_depth, z_what, W0, b0);
    k2_l1<<<NOBJ * 4, 128>>>(W1, b1);
    k3_l2l3<<<NOBJ * 4, 256>>>(W2, b2, W3, b3);
    decodeB_kernel<<<NOBJ * 4, 256>>>(W4, b4, W5, b5);

    dim3 cgrid(NTX * NTX, BATCH);
    composite_kernel<<<cgrid, 256>>>(z_where, z_present, out);
}

// round 12
// speedup vs baseline: 1.4487x; 1.4487x over previous
#include <cuda_runtime.h>
#include <math.h>

#define NLOC 1940
#define NPRI 8732
#define BATCH 16
#define TOPK 10
#define NOBJ (BATCH*TOPK)
#define DS 64
#define IMG 300
#define ZWHAT 64
#define CPAD 4
#define TILE 16
#define NTX ((IMG + TILE - 1) / TILE)   // 19

typedef unsigned long long ull;

// ---------------- device scratch (no allocation allowed) -------------------
__device__ __align__(16) float g_decoded[NOBJ * CPAD * DS * DS];   // 10.5 MB
__device__ int   g_order[BATCH * TOPK];

// ---------------- f32x2 helpers --------------------------------------------
__device__ __forceinline__ ull pack2(float lo, float hi) {
    ull r; asm("mov.b64 %0, {%1, %2};" : "=l"(r) : "f"(lo), "f"(hi)); return r;
}
__device__ __forceinline__ void unpack2(ull v, float& a, float& b) {
    asm("mov.b64 {%0, %1}, %2;" : "=f"(a), "=f"(b) : "l"(v));
}
__device__ __forceinline__ ull ffma2(ull a, ull b, ull c) {
    ull d; asm("fma.rn.f32x2 %0, %1, %2, %3;" : "=l"(d) : "l"(a), "l"(b), "l"(c));
    return d;
}
__device__ __forceinline__ ull relu2(ull v) {
    float a, b; unpack2(v, a, b);
    return pack2(fmaxf(a, 0.f), fmaxf(b, 0.f));
}

// ---------------- index maps ------------------------------------------------
__device__ __forceinline__ int prior_to_loc(int i) {
    if (i < 5776) return i >> 2;
    if (i < 7942) return 1444 + (i - 5776) / 6;
    if (i < 8542) return 1805 + (i - 7942) / 6;
    if (i < 8692) return 1905 + (i - 8542) / 6;
    if (i < 8728) return 1930 + ((i - 8692) >> 2);
    return 1939;
}
__device__ __forceinline__ void loc_to_priors(int l, int& start, int& bpl) {
    if (l < 1444)      { start = 4 * l;                 bpl = 4; }
    else if (l < 1805) { start = 5776 + 6 * (l - 1444); bpl = 6; }
    else if (l < 1905) { start = 7942 + 6 * (l - 1805); bpl = 6; }
    else if (l < 1930) { start = 8542 + 6 * (l - 1905); bpl = 6; }
    else               { start = 8692 + 4 * (l - 1930); bpl = 4; }
}
__device__ __forceinline__ bool better(float a, int ia, float b, int ib) {
    return a > b || (a == b && ia < ib);
}
__device__ __forceinline__ void insert3(float v, int i,
                                        float& v0, int& i0, float& v1, int& i1,
                                        float& v2, int& i2) {
    if (better(v, i, v0, i0)) { v2 = v1; i2 = i1; v1 = v0; i1 = i0; v0 = v; i0 = i; }
    else if (better(v, i, v1, i1)) { v2 = v1; i2 = i1; v1 = v; i1 = i; }
    else if (better(v, i, v2, i2)) { v2 = v; i2 = i; }
}

// block-redundant top-3 locations of batch b -> prior index of rank j.
// 512-thread version; scratch needs 512*6 floats.
__device__ __forceinline__ int block_topk512(const float* __restrict__ z_depth,
                                             int b, int j, float* scratch) {
    const int tid = threadIdx.x;
    float (*sv)[3] = (float(*)[3])scratch;
    int   (*si)[3] = (int(*)[3])(scratch + 512 * 3);

    float v0 = -INFINITY, v1 = -INFINITY, v2 = -INFINITY;
    int   i0 = 0x7fffffff, i1 = 0x7fffffff, i2 = 0x7fffffff;
    const float4* __restrict__ zd4 =
        reinterpret_cast<const float4*>(z_depth + b * NLOC);
    for (int i = tid; i < NLOC / 4; i += 512) {
        const float4 v = __ldg(zd4 + i);
        insert3(v.x, 4 * i + 0, v0, i0, v1, i1, v2, i2);
        insert3(v.y, 4 * i + 1, v0, i0, v1, i1, v2, i2);
        insert3(v.z, 4 * i + 2, v0, i0, v1, i1, v2, i2);
        insert3(v.w, 4 * i + 3, v0, i0, v1, i1, v2, i2);
    }
    sv[tid][0] = v0; sv[tid][1] = v1; sv[tid][2] = v2;
    si[tid][0] = i0; si[tid][1] = i1; si[tid][2] = i2;
    __syncthreads();
    for (int s = 256; s > 0; s >>= 1) {
        if (tid < s) {
            #pragma unroll
            for (int q = 0; q < 3; q++)
                insert3(sv[tid + s][q], si[tid + s][q], v0, i0, v1, i1, v2, i2);
            sv[tid][0] = v0; sv[tid][1] = v1; sv[tid][2] = v2;
            si[tid][0] = i0; si[tid][1] = i1; si[tid][2] = i2;
        }
        __syncthreads();
    }
    __shared__ int s_ord;
    if (tid == 0) {
        int ranks[3] = { i0, i1, i2 };
        int ord = -1, cnt = 0;
        #pragma unroll
        for (int r = 0; r < 3; r++) {
            int start, bpl;
            loc_to_priors(ranks[r], start, bpl);
            if (ord < 0 && j < cnt + bpl) ord = start + (j - cnt);
            cnt += bpl;
        }
        s_ord = ord;
    }
    __syncthreads();
    return s_ord;
}

// ---------------------------------------------------------------------------
// 512-thread quadrant-pair deconv layer: thread = (o = t%CO, y, x-half).
// CO*H*XS must equal 512. PX = W/XS input pixels per thread.
// Per c: 1 LDG.128 weight + PX input reads + 2*PX FFMA2.
// out[o, 2y+a, 2x+b] = bias[o] + sum_c in[c,y,x] * W[c,o,a,b]
// ---------------------------------------------------------------------------
template<int CI, int CO, int H, int W, int XS>
__device__ __forceinline__ void dlayer512(const float* __restrict__ in,
                                          float* __restrict__ out,
                                          const float* __restrict__ Wt,
                                          const float* __restrict__ bias)
{
    static_assert(CO * H * XS == 512, "thread mapping");
    constexpr int HW = H * W;
    constexpr int PX = W / XS;
    const int o   = threadIdx.x % CO;
    const int rem = threadIdx.x / CO;
    const int y   = rem % H;
    const int x0  = (rem / H) * PX;
    const ulonglong2* __restrict__ Wq = reinterpret_cast<const ulonglong2*>(Wt);
    const float bo = __ldg(bias + o);
    const ull bb = pack2(bo, bo);

    ull a01[PX], a23[PX];
    #pragma unroll
    for (int p = 0; p < PX; p++) { a01[p] = bb; a23[p] = bb; }

    const float* ip = in + y * W + x0;
    #pragma unroll 4
    for (int c = 0; c < CI; c++) {
        const ulonglong2 wq = __ldg(Wq + c * CO + o);   // (w0w1 | w2w3)
        if constexpr (PX == 1) {
            const float iv = ip[c * HW];
            const ull d = pack2(iv, iv);
            a01[0] = ffma2(d, wq.x, a01[0]);
            a23[0] = ffma2(d, wq.y, a23[0]);
        } else {
            const ull* __restrict__ ivp = reinterpret_cast<const ull*>(ip + c * HW);
            #pragma unroll
            for (int pp = 0; pp < PX / 2; pp++) {
                float i0, i1; unpack2(ivp[pp], i0, i1);
                const ull d0 = pack2(i0, i0);
                const ull d1 = pack2(i1, i1);
                a01[2 * pp]     = ffma2(d0, wq.x, a01[2 * pp]);
                a23[2 * pp]     = ffma2(d0, wq.y, a23[2 * pp]);
                a01[2 * pp + 1] = ffma2(d1, wq.x, a01[2 * pp + 1]);
                a23[2 * pp + 1] = ffma2(d1, wq.y, a23[2 * pp + 1]);
            }
        }
    }
    ull* r0 = reinterpret_cast<ull*>(out + (o * 2 * H + 2 * y) * (2 * W));
    ull* r1 = reinterpret_cast<ull*>(out + (o * 2 * H + 2 * y + 1) * (2 * W));
    #pragma unroll
    for (int p = 0; p < PX; p++) {
        r0[x0 + p] = relu2(a01[p]);
        r1[x0 + p] = relu2(a23[p]);
    }
}

// ---------------------------------------------------------------------------
// Decode kernel: topk + present-skip + L0..L5, one block per object, 512 thr.
// ---------------------------------------------------------------------------
__global__ void __launch_bounds__(512, 1) decode_kernel(
    const float* __restrict__ z_depth,
    const float* __restrict__ z_what,
    const int*   __restrict__ z_present,
    const float* __restrict__ W0, const float* __restrict__ b0,
    const float* __restrict__ W1, const float* __restrict__ b1,
    const float* __restrict__ W2, const float* __restrict__ b2,
    const float* __restrict__ W3, const float* __restrict__ b3,
    const float* __restrict__ W4, const float* __restrict__ b4,
    const float* __restrict__ W5, const float* __restrict__ b5)
{
    extern __shared__ __align__(16) float sm[];
    float* bufA = sm;           // up to 8192 floats
    float* bufB = sm + 8192;    // up to 16384 floats

    const int m = blockIdx.x;
    const int b = m / TOPK;
    const int j = m % TOPK;
    const int tid = threadIdx.x;

    const int ord = block_topk512(z_depth, b, j, bufB);
    if (tid == 0) g_order[m] = ord;

    // present-skip: composite never reads texels of non-present objects
    if (__ldg(z_present + b * NPRI + ord) != 1) return;

    const int loc = prior_to_loc(ord);
    const float* src = z_what + (size_t)(b * NLOC + loc) * ZWHAT;
    if (tid < ZWHAT) bufA[tid] = src[tid];
    __syncthreads();

    // ---- L0: 64 -> 256 ch, 1x1 -> 2x2 (threads 0..255) ----
    if (tid < 256) {
        const int o = tid;
        const ulonglong2* __restrict__ W0q = reinterpret_cast<const ulonglong2*>(W0);
        const float bo = __ldg(b0 + o);
        ull acc01 = pack2(bo, bo), acc23 = acc01;
        #pragma unroll 8
        for (int c = 0; c < 64; c++) {
            const ulonglong2 wq = __ldg(W0q + c * 256 + o);
            const ull ivd = pack2(bufA[c], bufA[c]);
            acc01 = ffma2(ivd, wq.x, acc01);
            acc23 = ffma2(ivd, wq.y, acc23);
        }
        ull* ob = reinterpret_cast<ull*>(bufB) + o * 2;
        ob[0] = relu2(acc01);   // [o][0][0..1]
        ob[1] = relu2(acc23);   // [o][1][0..1]
    }
    __syncthreads();

    dlayer512<256, 128,  2,  2, 2>(bufB, bufA, W1, b1); __syncthreads(); // 128x4x4
    dlayer512<128,  64,  4,  4, 2>(bufA, bufB, W2, b2); __syncthreads(); // 64x8x8
    dlayer512< 64,  32,  8,  8, 2>(bufB, bufA, W3, b3); __syncthreads(); // 32x16x16
    dlayer512< 32,  16, 16, 16, 2>(bufA, bufB, W4, b4); __syncthreads(); // 16x32x32

    // stage W5+b5 into bufA (free after L4 consumed it)
    if (tid < 192) bufA[tid] = __ldg(W5 + tid);
    if (tid < 3)   bufA[192 + tid] = __ldg(b5 + tid);
    __syncthreads();

    // ---- L5: 16 -> 3 ch, sigmoid, CPAD texels; 2 src px per thread ----
    {
        const int pbase = tid * 2;       // 0..1022
        const int sy = pbase >> 5;       // src row (32x32)
        const int sx = pbase & 31;       // src col (even)
        const ulonglong2* __restrict__ w5u =
            reinterpret_cast<const ulonglong2*>(bufA);
        ull a01[3][2], a23[3][2];
        #pragma unroll
        for (int o = 0; o < 3; o++) {
            const ull bb = pack2(bufA[192 + o], bufA[192 + o]);
            a01[o][0] = bb; a01[o][1] = bb;
            a23[o][0] = bb; a23[o][1] = bb;
        }
        #pragma unroll 4
        for (int c = 0; c < 16; c++) {
            const ull iv2 = *reinterpret_cast<const ull*>(bufB + c * 1024 + pbase);
            float i0, i1; unpack2(iv2, i0, i1);
            const ull d0 = pack2(i0, i0);
            const ull d1 = pack2(i1, i1);
            #pragma unroll
            for (int o = 0; o < 3; o++) {
                const ulonglong2 wq = w5u[c * 3 + o];
                a01[o][0] = ffma2(d0, wq.x, a01[o][0]);
                a23[o][0] = ffma2(d0, wq.y, a23[o][0]);
                a01[o][1] = ffma2(d1, wq.x, a01[o][1]);
                a23[o][1] = ffma2(d1, wq.y, a23[o][1]);
            }
        }
        float4* g4 = reinterpret_cast<float4*>(g_decoded) + (size_t)m * DS * DS;
        #pragma unroll
        for (int px = 0; px < 2; px++) {
            float rr[3][4];
            #pragma unroll
            for (int o = 0; o < 3; o++) {
                float v00, v01, v10, v11;
                unpack2(a01[o][px], v00, v01);
                unpack2(a23[o][px], v10, v11);
                rr[o][0] = 1.0f / (1.0f + __expf(-v00));
                rr[o][1] = 1.0f / (1.0f + __expf(-v01));
                rr[o][2] = 1.0f / (1.0f + __expf(-v10));
                rr[o][3] = 1.0f / (1.0f + __expf(-v11));
            }
            const int col0 = 2 * (sx + px);
            g4[(2 * sy) * DS + col0]         = make_float4(rr[0][0], rr[1][0], rr[2][0], 0.f);
            g4[(2 * sy) * DS + col0 + 1]     = make_float4(rr[0][1], rr[1][1], rr[2][1], 0.f);
            g4[(2 * sy + 1) * DS + col0]     = make_float4(rr[0][2], rr[1][2], rr[2][2], 0.f);
            g4[(2 * sy + 1) * DS + col0 + 1] = make_float4(rr[0][3], rr[1][3], rr[2][3], 0.f);
        }
    }
}

// ---------------------------------------------------------------------------
// Composite: fused STN + depth-ordered first-nonzero (unchanged, stable).
// ---------------------------------------------------------------------------
__global__ void __launch_bounds__(256) composite_kernel(
    const float* __restrict__ z_where,
    const int*   __restrict__ z_present,
    float* __restrict__ out)
{
    const int b = blockIdx.y;
    const int tx0 = (blockIdx.x % NTX) * TILE;
    const int ty0 = (blockIdx.x / NTX) * TILE;

    __shared__ float s_sx[TOPK], s_ox[TOPK], s_sy[TOPK], s_oy[TOPK];
    __shared__ int   s_flag[TOPK];
    __shared__ int   s_list[TOPK];
    __shared__ int   s_nc;

    const int tid = threadIdx.x;
    if (tid < TOPK) {
        const int ord = g_order[b * TOPK + tid];
        const float* zw = z_where + (size_t)(b * NPRI + ord) * 4;
        const float cx = zw[0], cy = zw[1];
        const float w = zw[2] + 1e-6f, h = zw[3] + 1e-6f;
        const float half = (float)DS * 0.5f;
        const float xsn = half / w;
        const float ysn = half / h;
        const float sx = xsn * (2.0f / (float)IMG);
        const float ox = half - 0.5f
                         + xsn * ((1.0f / (float)IMG - 1.0f) - (2.0f * cx - 1.0f));
        const float sy = ysn * (2.0f / (float)IMG);
        const float oy = half - 0.5f
                         + ysn * ((1.0f / (float)IMG - 1.0f) - (2.0f * cy - 1.0f));
        s_sx[tid] = sx; s_ox[tid] = ox; s_sy[tid] = sy; s_oy[tid] = oy;
        const float ix_lo = fmaf((float)tx0, sx, ox);
        const float ix_hi = fmaf((float)(tx0 + TILE - 1), sx, ox);
        const float iy_lo = fmaf((float)ty0, sy, oy);
        const float iy_hi = fmaf((float)(ty0 + TILE - 1), sy, oy);
        const bool pres = (z_present[b * NPRI + ord] == 1);
        s_flag[tid] = (pres &&
                       ix_hi >= -1.01f && ix_lo < 64.01f &&
                       iy_hi >= -1.01f && iy_lo < 64.01f) ? 1 : 0;
    }
    __syncthreads();
    if (tid == 0) {
        int nc = 0;
        #pragma unroll
        for (int k = 0; k < TOPK; k++)
            if (s_flag[k]) s_list[nc++] = k;
        s_nc = nc;
    }
    __syncthreads();

    const int x = tx0 + (tid % TILE);
    const int y = ty0 + (tid / TILE);
    if (x >= IMG || y >= IMG) return;
    const float fx = (float)x, fy = (float)y;

    float r0 = 0.0f, r1 = 0.0f, r2 = 0.0f;
    int done = 0;
    const int nc = s_nc;

    for (int kk = 0; kk < nc; kk++) {
        const int k = s_list[kk];
        const float ix = fmaf(fx, s_sx[k], s_ox[k]);
        const float iy = fmaf(fy, s_sy[k], s_oy[k]);
        const float ix0f = floorf(ix), iy0f = floorf(iy);
        if (!(ix0f >= -1.0f && ix0f <= 63.0f && iy0f >= -1.0f && iy0f <= 63.0f))
            continue;
        const float wx1 = ix - ix0f, wy1 = iy - iy0f;
        const float wx0 = 1.0f - wx1, wy0 = 1.0f - wy1;
        const int ix0 = (int)ix0f, iy0 = (int)iy0f;
        const bool vx0 = (ix0 >= 0), vx1 = (ix0 <= 62);
        const bool vy0 = (iy0 >= 0), vy1 = (iy0 <= 62);
        const float w00 = (vy0 && vx0) ? wy0 * wx0 : 0.0f;
        const float w01 = (vy0 && vx1) ? wy0 * wx1 : 0.0f;
        const float w10 = (vy1 && vx0) ? wy1 * wx0 : 0.0f;
        const float w11 = (vy1 && vx1) ? wy1 * wx1 : 0.0f;
        const int x0c = max(ix0, 0),     x1c = min(ix0 + 1, DS - 1);
        const int y0c = max(iy0, 0),     y1c = min(iy0 + 1, DS - 1);
        const int i00 = y0c * DS + x0c, i01 = y0c * DS + x1c;
        const int i10 = y1c * DS + x0c, i11 = y1c * DS + x1c;
        const float4* __restrict__ base = reinterpret_cast<const float4*>(g_decoded)
                                          + (size_t)(b * TOPK + k) * DS * DS;
        const float4 t00 = __ldg(base + i00);
        const float4 t01 = __ldg(base + i01);
        const float4 t10 = __ldg(base + i10);
        const float4 t11 = __ldg(base + i11);

        const float s0 = t00.x * w00 + t01.x * w01 + t10.x * w10 + t11.x * w11;
        const float s1 = t00.y * w00 + t01.y * w01 + t10.y * w10 + t11.y * w11;
        const float s2 = t00.z * w00 + t01.z * w01 + t10.z * w10 + t11.z * w11;

        if (!(done & 1) && s0 != 0.0f) { r0 = s0; done |= 1; }
        if (!(done & 2) && s1 != 0.0f) { r1 = s1; done |= 2; }
        if (!(done & 4) && s2 != 0.0f) { r2 = s2; done |= 4; }
        if (done == 7) break;
    }

    const size_t pix = (size_t)y * IMG + x;
    out[((size_t)(b * 3 + 0) * IMG * IMG) + pix] = r0;
    out[((size_t)(b * 3 + 1) * IMG * IMG) + pix] = r1;
    out[((size_t)(b * 3 + 2) * IMG * IMG) + pix] = r2;
}

// ---------------------------------------------------------------------------
extern "C" void kernel_launch(void* const* d_in, const int* in_sizes, int n_in,
                              void* d_out, int out_size)
{
    const float* z_what    = (const float*)d_in[0];
    const float* z_where   = (const float*)d_in[1];
    const int*   z_present = (const int*)  d_in[2];
    const float* z_depth   = (const float*)d_in[3];
    const float* W0 = (const float*)d_in[4];  const float* b0 = (const float*)d_in[5];
    const float* W1 = (const float*)d_in[6];  const float* b1 = (const float*)d_in[7];
    const float* W2 = (const float*)d_in[8];  const float* b2 = (const float*)d_in[9];
    const float* W3 = (const float*)d_in[10]; const float* b3 = (const float*)d_in[11];
    const float* W4 = (const float*)d_in[12]; const float* b4 = (const float*)d_in[13];
    const float* W5 = (const float*)d_in[14]; const float* b5 = (const float*)d_in[15];
    float* out = (float*)d_out;

    static bool attr_set = false;
    if (!attr_set) {
        cudaFuncSetAttribute(decode_kernel,
                             cudaFuncAttributeMaxDynamicSharedMemorySize,
                             (8192 + 16384) * sizeof(float));
        attr_set = true;
    }

    decode_kernel<<<NOBJ, 512, (8192 + 16384) * sizeof(float)>>>(
        z_depth, z_what, z_present,
        W0, b0, W1, b1, W2, b2, W3, b3, W4, b4, W5, b5);

    dim3 cgrid(NTX * NTX, BATCH);
    composite_kernel<<<cgrid, 256>>>(z_where, z_present, out);
}